// round 2
// baseline (speedup 1.0000x reference)
#include <cuda_runtime.h>
#include <math.h>

#define HASH_MASK ((1u << 19) - 1u)
#define P2 2654435761u
#define P3 805459861u

struct Res16 { int r[16]; };

__global__ __launch_bounds__(256)
void hashenc_kernel(const float* __restrict__ pos,
                    const float2* __restrict__ tab,
                    float2* __restrict__ out,
                    Res16 rp, int n)
{
    int i = blockIdx.x * blockDim.x + threadIdx.x;
    if (i >= n) return;

    float px = (pos[3 * i + 0] + 1.0f) * 0.5f;
    float py = (pos[3 * i + 1] + 1.0f) * 0.5f;
    float pz = (pos[3 * i + 2] + 1.0f) * 0.5f;

    #pragma unroll 4
    for (int l = 0; l < 16; ++l) {
        const int r  = rp.r[l];
        const int rm = r - 1;
        const float rm1 = (float)rm;

        float sx = px * rm1, sy = py * rm1, sz = pz * rm1;
        float fx = floorf(sx), fy = floorf(sy), fz = floorf(sz);
        float wx = sx - fx,   wy = sy - fy,   wz = sz - fz;
        int gx = (int)fx, gy = (int)fy, gz = (int)fz;

        int x0 = min(gx,     rm), x1 = min(gx + 1, rm);
        int y0 = min(gy,     rm), y1 = min(gy + 1, rm);
        int z0 = min(gz,     rm), z1 = min(gz + 1, rm);

        unsigned hx0 = (unsigned)x0;           // prime = 1
        unsigned hx1 = (unsigned)x1;
        unsigned hy0 = (unsigned)y0 * P2;
        unsigned hy1 = (unsigned)y1 * P2;
        unsigned hz0 = (unsigned)z0 * P3;
        unsigned hz1 = (unsigned)z1 * P3;

        // 8 independent gathers — MLP to hide L2 latency
        float2 f000 = __ldg(&tab[(hx0 ^ hy0 ^ hz0) & HASH_MASK]);
        float2 f001 = __ldg(&tab[(hx0 ^ hy0 ^ hz1) & HASH_MASK]);
        float2 f010 = __ldg(&tab[(hx0 ^ hy1 ^ hz0) & HASH_MASK]);
        float2 f011 = __ldg(&tab[(hx0 ^ hy1 ^ hz1) & HASH_MASK]);
        float2 f100 = __ldg(&tab[(hx1 ^ hy0 ^ hz0) & HASH_MASK]);
        float2 f101 = __ldg(&tab[(hx1 ^ hy0 ^ hz1) & HASH_MASK]);
        float2 f110 = __ldg(&tab[(hx1 ^ hy1 ^ hz0) & HASH_MASK]);
        float2 f111 = __ldg(&tab[(hx1 ^ hy1 ^ hz1) & HASH_MASK]);

        float ux = 1.0f - wx, uy = 1.0f - wy, uz = 1.0f - wz;
        float w000 = ux * uy * uz;
        float w001 = ux * uy * wz;
        float w010 = ux * wy * uz;
        float w011 = ux * wy * wz;
        float w100 = wx * uy * uz;
        float w101 = wx * uy * wz;
        float w110 = wx * wy * uz;
        float w111 = wx * wy * wz;

        float ax = 0.0f, ay = 0.0f;
        ax = fmaf(w000, f000.x, ax); ay = fmaf(w000, f000.y, ay);
        ax = fmaf(w001, f001.x, ax); ay = fmaf(w001, f001.y, ay);
        ax = fmaf(w010, f010.x, ax); ay = fmaf(w010, f010.y, ay);
        ax = fmaf(w011, f011.x, ax); ay = fmaf(w011, f011.y, ay);
        ax = fmaf(w100, f100.x, ax); ay = fmaf(w100, f100.y, ay);
        ax = fmaf(w101, f101.x, ax); ay = fmaf(w101, f101.y, ay);
        ax = fmaf(w110, f110.x, ax); ay = fmaf(w110, f110.y, ay);
        ax = fmaf(w111, f111.x, ax); ay = fmaf(w111, f111.y, ay);

        out[i * 16 + l] = make_float2(ax, ay);
    }
}

extern "C" void kernel_launch(void* const* d_in, const int* in_sizes, int n_in,
                              void* d_out, int out_size)
{
    const float*  pos = (const float*)d_in[0];
    const float2* tab = (const float2*)d_in[1];
    float2*       out = (float2*)d_out;

    const int n = in_sizes[0] / 3;

    // Mirror numpy: growth = exp((log(2048)-log(16))/15); res_l = min(int(16*growth**l), 2048)
    Res16 rp;
    const double growth = exp((log(2048.0) - log(16.0)) / 15.0);
    for (int l = 0; l < 16; ++l) {
        double v = 16.0 * pow(growth, (double)l);
        int r = (int)v;              // truncation, same as python int()
        rp.r[l] = r > 2048 ? 2048 : r;
    }

    const int threads = 256;
    const int blocks = (n + threads - 1) / threads;
    hashenc_kernel<<<blocks, threads>>>(pos, tab, out, rp, n);
}